// round 4
// baseline (speedup 1.0000x reference)
#include <cuda_runtime.h>
#include <math.h>

typedef unsigned long long ull;

#define BB 16      // batch
#define NN 500     // nodes
#define TT 128     // time steps
#define NP 512     // padded node stride
#define XGC 336    // padded channel count for 330-ch buffers (conv k-tile overread)
#define KT 16      // k-tile depth

// ---------------- scratch (static device globals; zero-initialized at load;
// pad regions are never written so they stay zero across all replays) --------
__device__ float g_H   [BB*64 *NP];
__device__ float g_XG5 [BB*XGC*NP];
__device__ float g_CG5 [BB*XGC*NP];
__device__ float g_XIN [BB*64 *NP];
__device__ float g_XIN2[BB*128*NP];
__device__ float g_GC  [BB*64 *NP];
__device__ float g_OUT [BB*64 *NP];
__device__ float g_U   [BB*64 *NP];

__device__ unsigned g_cnt;
__device__ volatile unsigned g_gen;

// ---------------- f32x2 helpers ----------------------------------------------
__device__ __forceinline__ ull pack2(float x, float y) {
    ull r; asm("mov.b64 %0, {%1,%2};" : "=l"(r) : "f"(x), "f"(y)); return r;
}
__device__ __forceinline__ void unpack2(ull p, float& x, float& y) {
    asm("mov.b64 {%0,%1}, %2;" : "=f"(x), "=f"(y) : "l"(p));
}
__device__ __forceinline__ void fma2(ull& d, ull a, ull b) {
    asm("fma.rn.f32x2 %0, %1, %2, %0;" : "+l"(d) : "l"(a), "l"(b));
}

// ---------------- software grid barrier (all blocks resident) -----------------
__device__ __forceinline__ void gridbar() {
    __syncthreads();
    if (threadIdx.x == 0) {
        unsigned gen = g_gen;              // volatile read BEFORE arriving
        __threadfence();
        if (atomicAdd(&g_cnt, 1u) == gridDim.x - 1u) {
            atomicExch(&g_cnt, 0u);        // reset for next barrier
            __threadfence();
            g_gen = gen + 1u;              // release
        } else {
            while (g_gen == gen) __nanosleep(64);
        }
        __threadfence();
    }
    __syncthreads();
}

// ---------------- 64x64 f32x2 micro-kernel ------------------------------------
// sA[k][m], sB[k][n]; thread (tx=tid&15 -> 4 n, ty=tid>>4 -> 4 m)
__device__ __forceinline__ void mm16(const float (*sA)[68], const float (*sB)[68],
                                     ull acc[4][2], int tx, int ty) {
#pragma unroll
    for (int kk = 0; kk < KT; kk++) {
        float4 a = *(const float4*)&sA[kk][ty * 4];
        ull b0 = *(const ull*)&sB[kk][tx * 4];
        ull b1 = *(const ull*)&sB[kk][tx * 4 + 2];
        ull ap;
        ap = pack2(a.x, a.x); fma2(acc[0][0], ap, b0); fma2(acc[0][1], ap, b1);
        ap = pack2(a.y, a.y); fma2(acc[1][0], ap, b0); fma2(acc[1][1], ap, b1);
        ap = pack2(a.z, a.z); fma2(acc[2][0], ap, b0); fma2(acc[2][1], ap, b1);
        ap = pack2(a.w, a.w); fma2(acc[3][0], ap, b0); fma2(acc[3][1], ap, b1);
    }
}

// =============================================================================
// Diffusion tile: dst[b, dstOff+c, w] = sum_v src[b, srcOff+c, v] * A[w, v]
// m = b*C + c (64 rows), n = w (64 cols), K = 500 (k-padded to 512 via zeros).
// =============================================================================
__device__ void diff_tile(const float* __restrict__ src, float* __restrict__ dst,
                          const float* __restrict__ A,
                          int C, int srcOff, int dstOff, int srcBS, int dstBS,
                          int m0, int n0,
                          float (*sA)[68], float (*sB)[68])
{
    const int tid = threadIdx.x;
    const int M = C * BB;
    const int r = tid >> 2;          // 0..63 (row within tile for loaders)
    const int kr = tid & 3;          // k-quarter
    const int koff = kr * 4;

    const float* srow = 0;
    {
        int gm = m0 + r;
        if (gm < M) {
            int b = gm / C, c = gm - b * C;
            srow = src + (size_t)b * srcBS + (size_t)(srcOff + c) * NP;
        }
    }
    const float* arow = 0;
    {
        int gn = n0 + r;
        if (gn < NN) arow = A + (size_t)gn * NN;
    }

    const int tx = tid & 15, ty = tid >> 4;
    ull acc[4][2] = {};

    const float4 Z = make_float4(0.f, 0.f, 0.f, 0.f);
    float4 va = srow ? *(const float4*)(srow + koff) : Z;                  // src padded to NP
    float4 vb = (arow && koff < NN) ? *(const float4*)(arow + koff) : Z;   // NN%4==0

    for (int k0 = 0; k0 < NN; k0 += KT) {
        __syncthreads();
        sA[kr*4+0][r] = va.x; sA[kr*4+1][r] = va.y;
        sA[kr*4+2][r] = va.z; sA[kr*4+3][r] = va.w;
        sB[kr*4+0][r] = vb.x; sB[kr*4+1][r] = vb.y;
        sB[kr*4+2][r] = vb.z; sB[kr*4+3][r] = vb.w;
        __syncthreads();
        int kn = k0 + KT;
        if (kn < NN) {
            va = srow ? *(const float4*)(srow + kn + koff) : Z;
            vb = (arow && kn + koff < NN) ? *(const float4*)(arow + kn + koff) : Z;
        }
        mm16(sA, sB, acc, tx, ty);
    }

#pragma unroll
    for (int i = 0; i < 4; i++) {
        int gm = m0 + ty * 4 + i;
        if (gm >= M) continue;
        int b = gm / C, c = gm - b * C;
        int gn = n0 + tx * 4;
        float* drow = dst + (size_t)b * dstBS + (size_t)(dstOff + c) * NP + gn;
        float v0, v1, v2, v3;
        unpack2(acc[i][0], v0, v1);
        unpack2(acc[i][1], v2, v3);
        if (gn + 3 < NN) { drow[0] = v0; drow[1] = v1; drow[2] = v2; drow[3] = v3; }
        else {
            if (gn     < NN) drow[0] = v0;
            if (gn + 1 < NN) drow[1] = v1;
            if (gn + 2 < NN) drow[2] = v2;
            if (gn + 3 < NN) drow[3] = v3;
        }
    }
}

// =============================================================================
// 1x1 conv tile: out[b,o,n] = act( sum_k W[o,k]*X[b,k,n] + bias[o] ), O=64.
// X = concat(S1[C1 ch], S2[...]). K-tiles may overread channels (buffers are
// channel-padded); Ws is zeroed for k>=K so overread contributes 0.
// modes: 0 plain->dstA | 1 prelu->OUT+reps | 2 sigmoid->U
//        3 sigmoid*h->CG5[2+o] | 4 tanh + h=u*h+(1-u)*c
// =============================================================================
__device__ void conv_tile(const float* __restrict__ S1, int C1, int s1BS,
                          const float* __restrict__ S2, int s2BS,
                          const float* __restrict__ W, const float* __restrict__ bias,
                          int K, int b, int n0, int mode, int t,
                          float* __restrict__ dstA,
                          float* __restrict__ reps, float prelu_a,
                          float (*sA)[68], float (*sB)[68])
{
    const int tid = threadIdx.x;
    const int o  = tid >> 2;           // Ws loader: output row
    const int kr = tid & 3;
    const int kx = tid >> 4;           // Xs loader: k within tile
    const int nc = (tid & 15) * 4;     // Xs loader: n chunk
    const int tx = tid & 15, ty = tid >> 4;

    ull acc[4][2] = {};

    float w0, w1, w2, w3;
    float4 vx;
    {
        int kg0 = kr * 4;
        w0 = (kg0 + 0 < K) ? W[(size_t)o * K + kg0 + 0] : 0.f;
        w1 = (kg0 + 1 < K) ? W[(size_t)o * K + kg0 + 1] : 0.f;
        w2 = (kg0 + 2 < K) ? W[(size_t)o * K + kg0 + 2] : 0.f;
        w3 = (kg0 + 3 < K) ? W[(size_t)o * K + kg0 + 3] : 0.f;
        int kg = kx;
        const float* row = (kg < C1) ? S1 + (size_t)b * s1BS + (size_t)kg * NP
                                     : S2 + (size_t)b * s2BS + (size_t)(kg - C1) * NP;
        vx = *(const float4*)(row + n0 + nc);
    }

    for (int k0 = 0; k0 < K; k0 += KT) {
        __syncthreads();
        sA[kr*4+0][o] = w0; sA[kr*4+1][o] = w1;
        sA[kr*4+2][o] = w2; sA[kr*4+3][o] = w3;
        *(float4*)&sB[kx][nc] = vx;
        __syncthreads();
        int kn = k0 + KT;
        if (kn < K) {
            int kg0 = kn + kr * 4;
            w0 = (kg0 + 0 < K) ? W[(size_t)o * K + kg0 + 0] : 0.f;
            w1 = (kg0 + 1 < K) ? W[(size_t)o * K + kg0 + 1] : 0.f;
            w2 = (kg0 + 2 < K) ? W[(size_t)o * K + kg0 + 2] : 0.f;
            w3 = (kg0 + 3 < K) ? W[(size_t)o * K + kg0 + 3] : 0.f;
            int kg = kn + kx;
            const float* row = (kg < C1) ? S1 + (size_t)b * s1BS + (size_t)kg * NP
                                         : S2 + (size_t)b * s2BS + (size_t)(kg - C1) * NP;
            vx = *(const float4*)(row + n0 + nc);
        }
        mm16(sA, sB, acc, tx, ty);
    }

#pragma unroll
    for (int i = 0; i < 4; i++) {
        int oo = ty * 4 + i;
        float bs = bias[oo];
        float v[4];
        unpack2(acc[i][0], v[0], v[1]);
        unpack2(acc[i][1], v[2], v[3]);
        int gn = n0 + tx * 4;
        size_t hidx = (size_t)b * 64 * NP + (size_t)oo * NP + gn;
#pragma unroll
        for (int j = 0; j < 4; j++) {
            if (gn + j >= NN) continue;
            float vv = v[j] + bs;
            if (mode == 0) {
                dstA[hidx + j] = vv;
            } else if (mode == 1) {
                vv = vv >= 0.f ? vv : prelu_a * vv;
                g_OUT[hidx + j] = vv;
                reps[(((size_t)(b * 128 + oo)) * NN + gn + j) * TT + t] = vv;
            } else if (mode == 2) {
                g_U[hidx + j] = 1.f / (1.f + expf(-vv));
            } else if (mode == 3) {
                float rr = 1.f / (1.f + expf(-vv));
                g_CG5[(size_t)b * XGC * NP + (size_t)(2 + oo) * NP + gn + j]
                    = rr * g_H[hidx + j];
            } else {
                float cc = tanhf(vv);
                float u = g_U[hidx + j];
                g_H[hidx + j] = u * g_H[hidx + j] + (1.f - u) * cc;
            }
        }
    }
}

// =============================================================================
// The persistent kernel: whole T-loop, grid barriers between stages.
// =============================================================================
__global__ void __launch_bounds__(256, 2) kmain(
    const float* __restrict__ x, const float* __restrict__ af,
    const float* __restrict__ ab, const int* __restrict__ mask,
    const float* __restrict__ Wr,  const float* __restrict__ br,
    const float* __restrict__ Wu,  const float* __restrict__ bu,
    const float* __restrict__ Wc,  const float* __restrict__ bc,
    const float* __restrict__ Wfs, const float* __restrict__ bfs,
    const float* __restrict__ Wli, const float* __restrict__ bli,
    const float* __restrict__ Wgc, const float* __restrict__ bgc,
    const float* __restrict__ Wlo, const float* __restrict__ blo,
    const float* __restrict__ Wro, const float* __restrict__ bro,
    const float* __restrict__ pa,
    float* __restrict__ imp, float* __restrict__ pred, float* __restrict__ reps)
{
    __shared__ float sA[KT][68];
    __shared__ float sB[KT][68];

    const int tid  = threadIdx.x;
    const int nb   = gridDim.x;
    const int gtid = blockIdx.x * 256 + tid;
    const int gstr = nb * 256;
    const float pav = *pa;

    // zero H (must happen every launch/replay)
    for (int i = gtid; i < BB * 64 * NP; i += gstr) g_H[i] = 0.f;
    gridbar();

    for (int t = 0; t < TT; t++) {
        // -------- stage A: pred, x1, mf; pack XG[0..65]; CG[1]; reps H-half ----
        for (int i = gtid; i < BB * NN; i += gstr) {
            int b = i / NN, n = i - b * NN;
            const float* h = g_H + (size_t)b * 64 * NP + n;
            float* xg = g_XG5 + (size_t)b * XGC * NP + n;
            float* rb = reps + (((size_t)(b * 128 + 64)) * NN + n) * TT + t;
            float s = bfs[0];
#pragma unroll 8
            for (int c = 0; c < 64; c++) {
                float hv = h[(size_t)c * NP];
                s += Wfs[c] * hv;
                xg[(size_t)(2 + c) * NP] = hv;
                rb[(size_t)c * NN * TT] = hv;
            }
            size_t xi = ((size_t)b * NN + n) * TT + t;
            pred[xi] = s;
            int mk = mask[xi];
            float x1 = mk ? x[xi] : s;
            xg[0]  = x1;
            xg[NP] = (float)mk;
            g_CG5[(size_t)b * XGC * NP + NP + n] = (float)mk;
        }
        gridbar();

        // -------- conv li: XG5[0..65] -> XIN ----------------------------------
        for (int tile = blockIdx.x; tile < 128; tile += nb) {
            int b = tile >> 3, n0 = (tile & 7) * 64;
            conv_tile(g_XG5, 1000, XGC * NP, 0, 0, Wli, bli, 66,
                      b, n0, 0, t, g_XIN, reps, pav, sA, sB);
        }
        gridbar();

        // -------- diffusion XIN -> XIN2 (Df|Db) -------------------------------
        for (int tile = blockIdx.x; tile < 256; tile += nb) {
            int z = tile >> 7, rem = tile & 127;
            int m0 = (rem >> 3) * 64, n0 = (rem & 7) * 64;
            diff_tile(g_XIN, g_XIN2, z ? ab : af, 64, 0, z * 64,
                      64 * NP, 128 * NP, m0, n0, sA, sB);
        }
        gridbar();

        // -------- conv gc: XIN2(128) -> GC ------------------------------------
        for (int tile = blockIdx.x; tile < 128; tile += nb) {
            int b = tile >> 3, n0 = (tile & 7) * 64;
            conv_tile(g_XIN2, 1000, 128 * NP, 0, 0, Wgc, bgc, 128,
                      b, n0, 0, t, g_GC, reps, pav, sA, sB);
        }
        gridbar();

        // -------- conv lo: [GC,H](128) -> OUT (prelu) + reps OUT-half ---------
        for (int tile = blockIdx.x; tile < 128; tile += nb) {
            int b = tile >> 3, n0 = (tile & 7) * 64;
            conv_tile(g_GC, 64, 64 * NP, g_H, 64 * NP, Wlo, blo, 128,
                      b, n0, 1, t, g_OUT, reps, pav, sA, sB);
        }
        gridbar();

        // -------- stage B: imp, x2 -> XG[0], CG[0] ----------------------------
        for (int i = gtid; i < BB * NN; i += gstr) {
            int b = i / NN, n = i - b * NN;
            const float* o = g_OUT + (size_t)b * 64 * NP + n;
            const float* h = g_H   + (size_t)b * 64 * NP + n;
            float s = bro[0];
#pragma unroll 8
            for (int c = 0; c < 64; c++)
                s += Wro[c] * o[(size_t)c * NP] + Wro[64 + c] * h[(size_t)c * NP];
            size_t xi = ((size_t)b * NN + n) * TT + t;
            imp[xi] = s;
            int mk = mask[xi];
            float* xg0 = g_XG5 + (size_t)b * XGC * NP + n;
            float x2 = mk ? *xg0 : s;
            *xg0 = x2;
            g_CG5[(size_t)b * XGC * NP + n] = x2;
        }
        gridbar();

        // -------- diffusion XG order-2 (2 stages) -----------------------------
        for (int tile = blockIdx.x; tile < 272; tile += nb) {
            int z = tile / 136, rem = tile - z * 136;
            int m0 = (rem >> 3) * 64, n0 = (rem & 7) * 64;
            diff_tile(g_XG5, g_XG5, z ? ab : af, 66, 0, 66 + z * 132,
                      XGC * NP, XGC * NP, m0, n0, sA, sB);
        }
        gridbar();
        for (int tile = blockIdx.x; tile < 272; tile += nb) {
            int z = tile / 136, rem = tile - z * 136;
            int m0 = (rem >> 3) * 64, n0 = (rem & 7) * 64;
            diff_tile(g_XG5, g_XG5, z ? ab : af, 66, 66 + z * 132, 132 + z * 132,
                      XGC * NP, XGC * NP, m0, n0, sA, sB);
        }
        gridbar();

        // -------- convs r (-> r*h into CG5[2..65]) and u (-> U) ---------------
        for (int tile = blockIdx.x; tile < 256; tile += nb) {
            int tl = tile & 127;
            int b = tl >> 3, n0 = (tl & 7) * 64;
            if (tile < 128)
                conv_tile(g_XG5, 1000, XGC * NP, 0, 0, Wr, br, 330,
                          b, n0, 3, t, g_U, reps, pav, sA, sB);
            else
                conv_tile(g_XG5, 1000, XGC * NP, 0, 0, Wu, bu, 330,
                          b, n0, 2, t, g_U, reps, pav, sA, sB);
        }
        gridbar();

        // -------- diffusion CG order-2 (2 stages) -----------------------------
        for (int tile = blockIdx.x; tile < 272; tile += nb) {
            int z = tile / 136, rem = tile - z * 136;
            int m0 = (rem >> 3) * 64, n0 = (rem & 7) * 64;
            diff_tile(g_CG5, g_CG5, z ? ab : af, 66, 0, 66 + z * 132,
                      XGC * NP, XGC * NP, m0, n0, sA, sB);
        }
        gridbar();
        for (int tile = blockIdx.x; tile < 272; tile += nb) {
            int z = tile / 136, rem = tile - z * 136;
            int m0 = (rem >> 3) * 64, n0 = (rem & 7) * 64;
            diff_tile(g_CG5, g_CG5, z ? ab : af, 66, 66 + z * 132, 132 + z * 132,
                      XGC * NP, XGC * NP, m0, n0, sA, sB);
        }
        gridbar();

        // -------- conv c (tanh) fused with h = u*h + (1-u)*c ------------------
        for (int tile = blockIdx.x; tile < 128; tile += nb) {
            int b = tile >> 3, n0 = (tile & 7) * 64;
            conv_tile(g_CG5, 1000, XGC * NP, 0, 0, Wc, bc, 330,
                      b, n0, 4, t, g_U, reps, pav, sA, sB);
        }
        gridbar();   // H update visible before next step's stage A
    }
}

// ---------------- launch ------------------------------------------------------
extern "C" void kernel_launch(void* const* d_in, const int* in_sizes, int n_in,
                              void* d_out, int out_size)
{
    const float* x    = (const float*)d_in[0];
    const float* af   = (const float*)d_in[1];
    const float* ab   = (const float*)d_in[2];
    const int*   mask = (const int*)  d_in[3];
    const float* Wr   = (const float*)d_in[4];
    const float* br   = (const float*)d_in[5];
    const float* Wu   = (const float*)d_in[6];
    const float* bu   = (const float*)d_in[7];
    const float* Wc   = (const float*)d_in[8];
    const float* bc   = (const float*)d_in[9];
    const float* Wfs  = (const float*)d_in[10];
    const float* bfs  = (const float*)d_in[11];
    const float* Wli  = (const float*)d_in[12];
    const float* bli  = (const float*)d_in[13];
    const float* Wgc  = (const float*)d_in[14];
    const float* bgc  = (const float*)d_in[15];
    const float* Wlo  = (const float*)d_in[16];
    const float* blo  = (const float*)d_in[17];
    const float* Wro  = (const float*)d_in[18];
    const float* bro  = (const float*)d_in[19];
    const float* pa   = (const float*)d_in[20];

    float* out_imp  = (float*)d_out;
    float* out_pred = out_imp + (size_t)BB * NN * TT;
    float* out_reps = out_imp + (size_t)2 * BB * NN * TT;

    int dev = 0; cudaGetDevice(&dev);
    int sm = 0;
    cudaDeviceGetAttribute(&sm, cudaDevAttrMultiProcessorCount, dev);
    if (sm <= 0) sm = 148;
    int per = 0;
    cudaOccupancyMaxActiveBlocksPerMultiprocessor(&per, kmain, 256, 0);
    if (per < 1) per = 1;
    if (per > 4) per = 4;
    int nb = sm * per;

    kmain<<<nb, 256>>>(x, af, ab, mask, Wr, br, Wu, bu, Wc, bc,
                       Wfs, bfs, Wli, bli, Wgc, bgc, Wlo, blo, Wro, bro, pa,
                       out_imp, out_pred, out_reps);
}